// round 3
// baseline (speedup 1.0000x reference)
#include <cuda_runtime.h>

// Steerable encoder: separable RBF, packed-f32x2 FMA accumulation,
// single persistent-wave kernel with software grid barrier for the
// cross-slice reduction + density normalization.
//
//  out0[k][j] = sum_i ex_ij * ey_ik
//  out1[k][j] = (sum_i ex_ij * ey_ik * Y_i0) / out0
//  out2[k][j] = (sum_i ex_ij * ey_ik * Y_i1) / out0

#define N_AXIS   128
#define NPIX     (N_AXIS * N_AXIS)     // 16384
#define NPTS     8192
#define NSLICE   55                    // 8 ktiles * 55 slices = 440 CTAs ~ 3/SM
#define NCTAS    (8 * NSLICE)          // 440 (all co-resident: 440 <= 3*148)
#define KT       16                    // k-rows per CTA
#define CI       128                   // i-chunk size

// partial sums: [slice][channel][k][j]
__device__ float g_partial[NSLICE * 3 * NPIX];
__device__ unsigned int g_arrive  = 0;
__device__ unsigned int g_release = 0;

__device__ __forceinline__ unsigned long long ffma2(unsigned long long a,
                                                    unsigned long long b,
                                                    unsigned long long c)
{
    unsigned long long d;
    asm("fma.rn.f32x2 %0, %1, %2, %3;" : "=l"(d) : "l"(a), "l"(b), "l"(c));
    return d;
}

__global__ __launch_bounds__(128, 3)
void se_fused_kernel(const float* __restrict__ X, const float* __restrict__ Y,
                     float* __restrict__ out)
{
    __shared__ float sh_a[CI][48];   // [i][k*3+c], row = 192B
    __shared__ float sh_x[CI];
    __shared__ unsigned int sh_rel0;

    const int j     = threadIdx.x;         // output column (x index)
    const int slice = blockIdx.x;          // i-slice (0..NSLICE-1)
    const int k0    = blockIdx.y * KT;     // first k-row of tile

    // snapshot release epoch before this CTA arrives (safe across replays)
    if (j == 0) sh_rel0 = *(volatile unsigned int*)&g_release;

    const float step = 4.0f / 127.0f;
    const float xj = -2.0f + (float)j * step;

    float yk[KT];
    #pragma unroll
    for (int k = 0; k < KT; k++) yk[k] = 2.0f - (float)(k0 + k) * step;

    unsigned long long acc[24];            // 48 packed f32 accumulators
    #pragma unroll
    for (int t = 0; t < 24; t++) acc[t] = 0ULL;

    const int lo = (NPTS * slice) / NSLICE;
    const int hi = (NPTS * (slice + 1)) / NSLICE;

    for (int base = lo; base < hi; base += CI) {
        const int cnt = min(CI, hi - base);

        // ---- cooperative fill: thread j handles point i = base + j ----
        if (j < cnt) {
            const int i = base + j;
            float2 xp = ((const float2*)X)[i];
            float2 yp = ((const float2*)Y)[i];
            sh_x[j] = xp.x;
            const float py = xp.y;
            #pragma unroll
            for (int k = 0; k < KT; k++) {
                float dy = yk[k] - py;
                float e  = __expf(-0.5f * dy * dy);
                sh_a[j][k * 3 + 0] = e;
                sh_a[j][k * 3 + 1] = e * yp.x;
                sh_a[j][k * 3 + 2] = e * yp.y;
            }
        }
        __syncthreads();

        // ---- main loop: 1 exp + 12 LDS.128 (broadcast) + 24 FFMA2 / i ----
        #pragma unroll 4
        for (int ii = 0; ii < cnt; ii++) {
            float dx = xj - sh_x[ii];
            float ef = __expf(-0.5f * dx * dx);
            unsigned int eb = __float_as_uint(ef);
            unsigned long long e2;
            asm("mov.b64 %0, {%1, %1};" : "=l"(e2) : "r"(eb));

            const ulonglong2* row = (const ulonglong2*)sh_a[ii];
            #pragma unroll
            for (int u = 0; u < 12; u++) {
                ulonglong2 v = row[u];
                acc[2 * u + 0] = ffma2(e2, v.x, acc[2 * u + 0]);
                acc[2 * u + 1] = ffma2(e2, v.y, acc[2 * u + 1]);
            }
        }
        __syncthreads();
    }

    // ---- unpack + write partial sums (coalesced in j) ----
    float res[48];
    #pragma unroll
    for (int u = 0; u < 24; u++) {
        res[2 * u + 0] = __uint_as_float((unsigned int)(acc[u] & 0xffffffffULL));
        res[2 * u + 1] = __uint_as_float((unsigned int)(acc[u] >> 32));
    }

    float* p = g_partial + slice * (3 * NPIX);
    #pragma unroll
    for (int t = 0; t < 48; t++) {
        int k = t / 3, c = t % 3;
        p[c * NPIX + (k0 + k) * N_AXIS + j] = res[t];
    }

    // ---- software grid barrier (all NCTAS co-resident in wave 1) ----
    __threadfence();       // partials visible GPU-wide
    __syncthreads();       // all threads of this CTA done writing
    if (j == 0) {
        unsigned int old = atomicAdd(&g_arrive, 1u);
        if (old == NCTAS - 1) {
            g_arrive = 0;              // sole writer at this point
            __threadfence();
            atomicAdd(&g_release, 1u);
        }
        while (*(volatile unsigned int*)&g_release == sh_rel0) { }
    }
    __syncthreads();
    __threadfence();

    // ---- cross-slice reduction + normalization (partials are L2-hot) ----
    const int bid = blockIdx.y * gridDim.x + blockIdx.x;
    const int g   = bid * 128 + j;         // 0 .. 440*128-1
    if (g < NPIX) {
        float s0 = 0.0f, s1 = 0.0f, s2 = 0.0f;
        #pragma unroll 5
        for (int s = 0; s < NSLICE; s++) {
            const float* b = g_partial + s * (3 * NPIX);
            s0 += __ldcg(b + g);
            s1 += __ldcg(b + NPIX + g);
            s2 += __ldcg(b + 2 * NPIX + g);
        }
        float r = 1.0f / s0;
        out[g]            = s0;
        out[NPIX + g]     = s1 * r;
        out[2 * NPIX + g] = s2 * r;
    }
}

extern "C" void kernel_launch(void* const* d_in, const int* in_sizes, int n_in,
                              void* d_out, int out_size)
{
    const float* X = (const float*)d_in[0];
    const float* Y = (const float*)d_in[1];
    float* out = (float*)d_out;

    dim3 grid(NSLICE, N_AXIS / KT);   // 55 x 8 = 440 CTAs, all resident at occ 3
    se_fused_kernel<<<grid, 128>>>(X, Y, out);
}